// round 1
// baseline (speedup 1.0000x reference)
#include <cuda_runtime.h>
#include <cstddef>

#define D 128
#define MAXG 100000

// scratch (device globals — no allocation allowed)
__device__ int   g_last[MAXG];
__device__ float g_A[D * D];
__device__ float g_bp[D];
__device__ float g_p[(size_t)MAXG * D];
__device__ float g_s[(size_t)MAXG * D];

// -------------------------------------------------------------------------
// 1) segment boundaries: last index of each (sorted, contiguous) segment
// -------------------------------------------------------------------------
__global__ void bounds_kernel(const int* __restrict__ seg, int N) {
    int i = blockIdx.x * blockDim.x + threadIdx.x;
    if (i < N) {
        int sid = seg[i];
        if (i == N - 1 || seg[i + 1] != sid) g_last[sid] = i;
    }
}

// -------------------------------------------------------------------------
// 2) A = Wq^T @ Wk  (so p = e_last @ A + bq @ Wk), b' = bq @ Wk
// -------------------------------------------------------------------------
__global__ void prep_kernel(const float* __restrict__ Wq, const float* __restrict__ bq,
                            const float* __restrict__ Wk) {
    int t = threadIdx.x;
    if (blockIdx.x < 64) {
        int idx = blockIdx.x * 256 + t;
        int i = idx >> 7, j = idx & 127;
        float sum = 0.f;
#pragma unroll 8
        for (int d = 0; d < D; d++) sum += Wq[d * D + i] * Wk[d * D + j];
        g_A[idx] = sum;
    } else if (t < D) {
        float sum = 0.f;
#pragma unroll 8
        for (int d = 0; d < D; d++) sum += bq[d] * Wk[d * D + t];
        g_bp[t] = sum;
    }
}

// -------------------------------------------------------------------------
// SIMT SGEMM: C[M,128] = srcRows(Amat) @ B + bias
//   GATHER: row m of A is Amat[ridx[m]]
//   TRANSB: B_kj = Bmat[j*128 + k]   (i.e. Bmat row-major [j][k], use B^T)
// tile 128x128, 256 threads, 8x8 per thread, K-step 16
// -------------------------------------------------------------------------
template <bool GATHER, bool TRANSB>
__global__ void __launch_bounds__(256, 2)
gemm_kernel(const float* __restrict__ Amat, const float* __restrict__ Bmat,
            const float* __restrict__ bias, const int* __restrict__ ridx,
            float* __restrict__ Cmat, int M) {
    __shared__ float As[16][132];
    __shared__ float Bs[16][132];
    int t  = threadIdx.x;
    int tx = t & 15, ty = t >> 4;
    int mBase = blockIdx.x * 128;

    int lmA  = t >> 2;          // 0..63
    int kk4  = (t & 3) << 2;    // 0,4,8,12
    size_t rowA0, rowA1;
    {
        int m0 = mBase + lmA, m1 = m0 + 64;
        int r0 = (m0 < M) ? (GATHER ? ridx[m0] : m0) : 0;
        int r1 = (m1 < M) ? (GATHER ? ridx[m1] : m1) : 0;
        rowA0 = (size_t)r0 * D;
        rowA1 = (size_t)r1 * D;
    }

    float acc[8][8];
#pragma unroll
    for (int i = 0; i < 8; i++)
#pragma unroll
        for (int j = 0; j < 8; j++) acc[i][j] = 0.f;

    for (int k0 = 0; k0 < D; k0 += 16) {
        // A tile (transposed into shared: As[kk][m_local])
        float4 a0 = *(const float4*)(Amat + rowA0 + k0 + kk4);
        float4 a1 = *(const float4*)(Amat + rowA1 + k0 + kk4);
        As[kk4 + 0][lmA] = a0.x; As[kk4 + 1][lmA] = a0.y;
        As[kk4 + 2][lmA] = a0.z; As[kk4 + 3][lmA] = a0.w;
        As[kk4 + 0][lmA + 64] = a1.x; As[kk4 + 1][lmA + 64] = a1.y;
        As[kk4 + 2][lmA + 64] = a1.z; As[kk4 + 3][lmA + 64] = a1.w;

        if (!TRANSB) {
            int kk = t >> 5, j4 = (t & 31) << 2;
            *(float4*)&Bs[kk][j4]     = *(const float4*)(Bmat + (k0 + kk) * D + j4);
            *(float4*)&Bs[kk + 8][j4] = *(const float4*)(Bmat + (k0 + kk + 8) * D + j4);
        } else {
            int j = t >> 2;
            float4 b0 = *(const float4*)(Bmat + j * D + k0 + kk4);
            float4 b1 = *(const float4*)(Bmat + (j + 64) * D + k0 + kk4);
            Bs[kk4 + 0][j] = b0.x; Bs[kk4 + 1][j] = b0.y;
            Bs[kk4 + 2][j] = b0.z; Bs[kk4 + 3][j] = b0.w;
            Bs[kk4 + 0][j + 64] = b1.x; Bs[kk4 + 1][j + 64] = b1.y;
            Bs[kk4 + 2][j + 64] = b1.z; Bs[kk4 + 3][j + 64] = b1.w;
        }
        __syncthreads();

#pragma unroll
        for (int kk = 0; kk < 16; kk++) {
            float4 av0 = *(float4*)&As[kk][ty << 3];
            float4 av1 = *(float4*)&As[kk][(ty << 3) + 4];
            float4 bv0 = *(float4*)&Bs[kk][tx << 3];
            float4 bv1 = *(float4*)&Bs[kk][(tx << 3) + 4];
            float a[8] = {av0.x, av0.y, av0.z, av0.w, av1.x, av1.y, av1.z, av1.w};
            float b[8] = {bv0.x, bv0.y, bv0.z, bv0.w, bv1.x, bv1.y, bv1.z, bv1.w};
#pragma unroll
            for (int i = 0; i < 8; i++)
#pragma unroll
                for (int j = 0; j < 8; j++) acc[i][j] += a[i] * b[j];
        }
        __syncthreads();
    }

    float bl[8];
#pragma unroll
    for (int j = 0; j < 8; j++) bl[j] = bias[(tx << 3) + j];
#pragma unroll
    for (int i = 0; i < 8; i++) {
        int m = mBase + (ty << 3) + i;
        if (m < M) {
            float4 o0 = {acc[i][0] + bl[0], acc[i][1] + bl[1],
                         acc[i][2] + bl[2], acc[i][3] + bl[3]};
            float4 o1 = {acc[i][4] + bl[4], acc[i][5] + bl[5],
                         acc[i][6] + bl[6], acc[i][7] + bl[7]};
            *(float4*)(Cmat + (size_t)m * D + (tx << 3))     = o0;
            *(float4*)(Cmat + (size_t)m * D + (tx << 3) + 4) = o1;
        }
    }
}

// -------------------------------------------------------------------------
// 4) fused per-segment online softmax + weighted embedding sum.
//    one warp per group; logits_i = p_g . e_i ; s_g = sum w_i e_i
// -------------------------------------------------------------------------
__global__ void seg_softmax_kernel(const float* __restrict__ emb, int G) {
    int w = (blockIdx.x * blockDim.x + threadIdx.x) >> 5;
    int lane = threadIdx.x & 31;
    if (w >= G) return;

    int start = (w == 0) ? 0 : (g_last[w - 1] + 1);
    int end   = g_last[w];

    float4 pv = *(const float4*)(g_p + (size_t)w * D + (lane << 2));

    const float4* erow = (const float4*)emb;  // index = r*32 + lane
    float4 cur = erow[(size_t)start * 32 + lane];

    float m = -1e30f, denom = 0.f;
    float4 acc = {0.f, 0.f, 0.f, 0.f};

    for (int r = start; r <= end; r++) {
        float4 nxt = cur;
        if (r < end) nxt = erow[(size_t)(r + 1) * 32 + lane];  // prefetch

        float partial = cur.x * pv.x + cur.y * pv.y + cur.z * pv.z + cur.w * pv.w;
#pragma unroll
        for (int off = 16; off > 0; off >>= 1)
            partial += __shfl_xor_sync(0xffffffffu, partial, off);
        float logit = partial;

        float mnew  = fmaxf(m, logit);
        float scale = __expf(m - mnew);       // first iter: exp(-huge) -> 0
        float wgt   = __expf(logit - mnew);
        denom = denom * scale + wgt;
        acc.x = acc.x * scale + wgt * cur.x;
        acc.y = acc.y * scale + wgt * cur.y;
        acc.z = acc.z * scale + wgt * cur.z;
        acc.w = acc.w * scale + wgt * cur.w;
        m = mnew;
        cur = nxt;
    }

    float inv = 1.0f / denom;
    float4 o = {acc.x * inv, acc.y * inv, acc.z * inv, acc.w * inv};
    *(float4*)(g_s + (size_t)w * D + (lane << 2)) = o;
}

// -------------------------------------------------------------------------
extern "C" void kernel_launch(void* const* d_in, const int* in_sizes, int n_in,
                              void* d_out, int out_size) {
    const float* emb = (const float*)d_in[0];
    const int*   seg = (const int*)d_in[1];
    const float* Wq  = (const float*)d_in[2];
    const float* bq  = (const float*)d_in[3];
    const float* Wk  = (const float*)d_in[4];
    const float* bk  = (const float*)d_in[5];
    float* out = (float*)d_out;

    int N = in_sizes[0] / D;
    int G = out_size / D;

    void *pLast, *pA, *pBp, *pP, *pS;
    cudaGetSymbolAddress(&pLast, g_last);
    cudaGetSymbolAddress(&pA, g_A);
    cudaGetSymbolAddress(&pBp, g_bp);
    cudaGetSymbolAddress(&pP, g_p);
    cudaGetSymbolAddress(&pS, g_s);

    bounds_kernel<<<(N + 255) / 256, 256>>>(seg, N);
    prep_kernel<<<65, 256>>>(Wq, bq, Wk);

    // p[G,128] = emb[last] @ A + b'
    gemm_kernel<true, false><<<(G + 127) / 128, 256>>>(
        emb, (const float*)pA, (const float*)pBp, (const int*)pLast, (float*)pP, G);

    // fused segment softmax -> s[G,128] (weighted mean of embeddings)
    seg_softmax_kernel<<<(G + 7) / 8, 256>>>(emb, G);

    // out = s @ Wk^T + bk
    gemm_kernel<false, true><<<(G + 127) / 128, 256>>>(
        (const float*)pS, Wk, bk, nullptr, out, G);
}

// round 2
// speedup vs baseline: 1.1950x; 1.1950x over previous
#include <cuda_runtime.h>
#include <cuda_bf16.h>
#include <cstddef>
#include <cstdint>

#define D 128
#define MAXG 100000

// scratch (device globals — no allocation allowed)
__device__ int   g_last[MAXG];
__device__ float g_A[D * D];
__device__ float g_bp[D];
__device__ float g_p[(size_t)MAXG * D];
__device__ float g_s[(size_t)MAXG * D];
// bf16 hi/lo splits of the two B matrices, stored as b_eff[n][k]
__device__ __nv_bfloat16 g_B1h[D * D], g_B1l[D * D];
__device__ __nv_bfloat16 g_B2h[D * D], g_B2l[D * D];

// -------------------------------------------------------------------------
// 1) segment boundaries
// -------------------------------------------------------------------------
__global__ void bounds_kernel(const int* __restrict__ seg, int N) {
    int i = blockIdx.x * blockDim.x + threadIdx.x;
    if (i < N) {
        int sid = seg[i];
        if (i == N - 1 || seg[i + 1] != sid) g_last[sid] = i;
    }
}

// -------------------------------------------------------------------------
// 2) A = Wq^T @ Wk, b' = bq @ Wk
// -------------------------------------------------------------------------
__global__ void prep_kernel(const float* __restrict__ Wq, const float* __restrict__ bq,
                            const float* __restrict__ Wk) {
    int t = threadIdx.x;
    if (blockIdx.x < 64) {
        int idx = blockIdx.x * 256 + t;
        int i = idx >> 7, j = idx & 127;
        float sum = 0.f;
#pragma unroll 8
        for (int d = 0; d < D; d++) sum += Wq[d * D + i] * Wk[d * D + j];
        g_A[idx] = sum;
    } else if (t < D) {
        float sum = 0.f;
#pragma unroll 8
        for (int d = 0; d < D; d++) sum += bq[d] * Wk[d * D + t];
        g_bp[t] = sum;
    }
}

// -------------------------------------------------------------------------
// 2b) bf16 hi/lo split of both B matrices (b_eff[n][k] layout)
//     B1: b_eff1[n][k] = Aqk[k][n]   (p = E_last @ Aqk)
//     B2: b_eff2[n][k] = Wk[n][k]    (out = s @ Wk^T)
// -------------------------------------------------------------------------
__global__ void split_kernel(const float* __restrict__ Wk) {
    int idx = blockIdx.x * 256 + threadIdx.x;   // 0..16383
    int n = idx >> 7, k = idx & 127;
    float v1 = g_A[k * D + n];
    __nv_bfloat16 h1 = __float2bfloat16(v1);
    g_B1h[idx] = h1;
    g_B1l[idx] = __float2bfloat16(v1 - __bfloat162float(h1));
    float v2 = Wk[idx];                          // Wk[n][k]
    __nv_bfloat16 h2 = __float2bfloat16(v2);
    g_B2h[idx] = h2;
    g_B2l[idx] = __float2bfloat16(v2 - __bfloat162float(h2));
}

// -------------------------------------------------------------------------
// Tensor-core GEMM: C[M,128] = rows(Amat) @ b_eff^T + bias
//   3-term bf16 split: hi*hi + lo*hi + hi*lo, fp32 accumulate.
//   128x128 tile, 256 threads (8 warps), warp tile 16x128.
// -------------------------------------------------------------------------
#define MMA_BF16(cc, a0, a1, a2, a3, b0, b1)                                  \
    asm volatile(                                                             \
        "mma.sync.aligned.m16n8k16.row.col.f32.bf16.bf16.f32 "                \
        "{%0,%1,%2,%3}, {%4,%5,%6,%7}, {%8,%9}, {%0,%1,%2,%3};"               \
        : "+f"(cc[0]), "+f"(cc[1]), "+f"(cc[2]), "+f"(cc[3])                  \
        : "r"(a0), "r"(a1), "r"(a2), "r"(a3), "r"(b0), "r"(b1))

__device__ __forceinline__ uint32_t lds_u32(const __nv_bfloat16* s, int e) {
    return *(const uint32_t*)(s + e);
}

__global__ void __launch_bounds__(256, 2)
mma_gemm_kernel(const float* __restrict__ Amat,
                const __nv_bfloat16* __restrict__ Bh,
                const __nv_bfloat16* __restrict__ Bl,
                const float* __restrict__ bias,
                const int* __restrict__ ridx,
                float* __restrict__ C, int M) {
    constexpr int KC = 32;          // k-chunk
    constexpr int SST = KC + 4;     // shared stride (bf16 elems) = 36
    __shared__ __nv_bfloat16 sAh[128 * SST], sAl[128 * SST];
    __shared__ __nv_bfloat16 sBh[128 * SST], sBl[128 * SST];
    __shared__ float sBias[128];

    int t = threadIdx.x;
    int mBase = blockIdx.x * 128;
    if (t < 128) sBias[t] = bias[t];

    int lane = t & 31, warp = t >> 5;
    int g = lane >> 2, p = lane & 3;
    int m0 = warp * 16;

    float acc[16][4];
#pragma unroll
    for (int nb = 0; nb < 16; nb++)
#pragma unroll
        for (int i = 0; i < 4; i++) acc[nb][i] = 0.f;

    // load mapping: 2 threads per row, 16 k each
    int lm = t >> 1;
    int kseg = (t & 1) * 16;
    int mrow = mBase + lm;
    if (mrow >= M) mrow = M - 1;
    int arow = ridx ? ridx[mrow] : mrow;
    const float* aptr = Amat + (size_t)arow * D;

#pragma unroll 1
    for (int kc = 0; kc < 4; kc++) {
        int k0 = kc * KC;
        if (kc) __syncthreads();

        // stage A chunk with on-the-fly bf16 split
        int sbase = lm * SST + kseg;
#pragma unroll
        for (int i = 0; i < 4; i++) {
            float4 v = *(const float4*)(aptr + k0 + kseg + i * 4);
            __nv_bfloat16 hx = __float2bfloat16(v.x);
            __nv_bfloat16 hy = __float2bfloat16(v.y);
            __nv_bfloat16 hz = __float2bfloat16(v.z);
            __nv_bfloat16 hw = __float2bfloat16(v.w);
            *(__nv_bfloat162*)(sAh + sbase + i * 4)     = {hx, hy};
            *(__nv_bfloat162*)(sAh + sbase + i * 4 + 2) = {hz, hw};
            *(__nv_bfloat162*)(sAl + sbase + i * 4) = {
                __float2bfloat16(v.x - __bfloat162float(hx)),
                __float2bfloat16(v.y - __bfloat162float(hy))};
            *(__nv_bfloat162*)(sAl + sbase + i * 4 + 2) = {
                __float2bfloat16(v.z - __bfloat162float(hz)),
                __float2bfloat16(v.w - __bfloat162float(hw))};
        }
        // stage B chunk (already bf16 in global, L2-resident)
        {
            const __nv_bfloat16* bhp = Bh + lm * D + k0 + kseg;
            const __nv_bfloat16* blp = Bl + lm * D + k0 + kseg;
            uint4 h0 = *(const uint4*)(bhp);
            uint4 h1 = *(const uint4*)(bhp + 8);
            uint4 l0 = *(const uint4*)(blp);
            uint4 l1 = *(const uint4*)(blp + 8);
            uint2* dh = (uint2*)(sBh + sbase);
            uint2* dl = (uint2*)(sBl + sbase);
            dh[0] = {h0.x, h0.y}; dh[1] = {h0.z, h0.w};
            dh[2] = {h1.x, h1.y}; dh[3] = {h1.z, h1.w};
            dl[0] = {l0.x, l0.y}; dl[1] = {l0.z, l0.w};
            dl[2] = {l1.x, l1.y}; dl[3] = {l1.z, l1.w};
        }
        __syncthreads();

#pragma unroll
        for (int ks = 0; ks < 2; ks++) {
            int kb = ks * 16 + p * 2;
            int r0 = (m0 + g) * SST + kb;
            int r1 = (m0 + g + 8) * SST + kb;
            uint32_t ah0 = lds_u32(sAh, r0);
            uint32_t ah1 = lds_u32(sAh, r1);
            uint32_t ah2 = lds_u32(sAh, r0 + 8);
            uint32_t ah3 = lds_u32(sAh, r1 + 8);
            uint32_t al0 = lds_u32(sAl, r0);
            uint32_t al1 = lds_u32(sAl, r1);
            uint32_t al2 = lds_u32(sAl, r0 + 8);
            uint32_t al3 = lds_u32(sAl, r1 + 8);
#pragma unroll
            for (int nb = 0; nb < 16; nb++) {
                int nB = (nb * 8 + g) * SST + kb;
                uint32_t bh0 = lds_u32(sBh, nB);
                uint32_t bh1 = lds_u32(sBh, nB + 8);
                uint32_t bl0 = lds_u32(sBl, nB);
                uint32_t bl1 = lds_u32(sBl, nB + 8);
                MMA_BF16(acc[nb], ah0, ah1, ah2, ah3, bh0, bh1);
                MMA_BF16(acc[nb], al0, al1, al2, al3, bh0, bh1);
                MMA_BF16(acc[nb], ah0, ah1, ah2, ah3, bl0, bl1);
            }
        }
    }

    // epilogue: add bias, store
    int row0 = mBase + m0 + g;
    int row1 = row0 + 8;
#pragma unroll
    for (int nb = 0; nb < 16; nb++) {
        int col = nb * 8 + p * 2;
        float b0 = sBias[col], b1 = sBias[col + 1];
        if (row0 < M) {
            float2 o = {acc[nb][0] + b0, acc[nb][1] + b1};
            *(float2*)(C + (size_t)row0 * D + col) = o;
        }
        if (row1 < M) {
            float2 o = {acc[nb][2] + b0, acc[nb][3] + b1};
            *(float2*)(C + (size_t)row1 * D + col) = o;
        }
    }
}

// -------------------------------------------------------------------------
// 4) fused per-segment online softmax + weighted embedding sum (1 warp/group)
// -------------------------------------------------------------------------
__global__ void seg_softmax_kernel(const float* __restrict__ emb, int G) {
    int w = (blockIdx.x * blockDim.x + threadIdx.x) >> 5;
    int lane = threadIdx.x & 31;
    if (w >= G) return;

    int start = (w == 0) ? 0 : (g_last[w - 1] + 1);
    int end   = g_last[w];

    float4 pv = *(const float4*)(g_p + (size_t)w * D + (lane << 2));

    const float4* erow = (const float4*)emb;  // index = r*32 + lane
    float4 cur = erow[(size_t)start * 32 + lane];

    float m = -1e30f, denom = 0.f;
    float4 acc = {0.f, 0.f, 0.f, 0.f};

    for (int r = start; r <= end; r++) {
        float4 nxt = cur;
        if (r < end) nxt = erow[(size_t)(r + 1) * 32 + lane];  // prefetch

        float partial = cur.x * pv.x + cur.y * pv.y + cur.z * pv.z + cur.w * pv.w;
#pragma unroll
        for (int off = 16; off > 0; off >>= 1)
            partial += __shfl_xor_sync(0xffffffffu, partial, off);
        float logit = partial;

        float mnew  = fmaxf(m, logit);
        float scale = __expf(m - mnew);
        float wgt   = __expf(logit - mnew);
        denom = denom * scale + wgt;
        acc.x = acc.x * scale + wgt * cur.x;
        acc.y = acc.y * scale + wgt * cur.y;
        acc.z = acc.z * scale + wgt * cur.z;
        acc.w = acc.w * scale + wgt * cur.w;
        m = mnew;
        cur = nxt;
    }

    float inv = 1.0f / denom;
    float4 o = {acc.x * inv, acc.y * inv, acc.z * inv, acc.w * inv};
    *(float4*)(g_s + (size_t)w * D + (lane << 2)) = o;
}

// -------------------------------------------------------------------------
extern "C" void kernel_launch(void* const* d_in, const int* in_sizes, int n_in,
                              void* d_out, int out_size) {
    const float* emb = (const float*)d_in[0];
    const int*   seg = (const int*)d_in[1];
    const float* Wq  = (const float*)d_in[2];
    const float* bq  = (const float*)d_in[3];
    const float* Wk  = (const float*)d_in[4];
    const float* bk  = (const float*)d_in[5];
    float* out = (float*)d_out;

    int N = in_sizes[0] / D;
    int G = out_size / D;

    void *pLast, *pBp, *pP, *pS, *pB1h, *pB1l, *pB2h, *pB2l;
    cudaGetSymbolAddress(&pLast, g_last);
    cudaGetSymbolAddress(&pBp, g_bp);
    cudaGetSymbolAddress(&pP, g_p);
    cudaGetSymbolAddress(&pS, g_s);
    cudaGetSymbolAddress(&pB1h, g_B1h);
    cudaGetSymbolAddress(&pB1l, g_B1l);
    cudaGetSymbolAddress(&pB2h, g_B2h);
    cudaGetSymbolAddress(&pB2l, g_B2l);

    bounds_kernel<<<(N + 255) / 256, 256>>>(seg, N);
    prep_kernel<<<65, 256>>>(Wq, bq, Wk);
    split_kernel<<<64, 256>>>(Wk);

    // p[G,128] = emb[last] @ Aqk + b'
    mma_gemm_kernel<<<(G + 127) / 128, 256>>>(
        emb, (const __nv_bfloat16*)pB1h, (const __nv_bfloat16*)pB1l,
        (const float*)pBp, (const int*)pLast, (float*)pP, G);

    // fused segment softmax -> s[G,128]
    seg_softmax_kernel<<<(G + 7) / 8, 256>>>(emb, G);

    // out = s @ Wk^T + bk
    mma_gemm_kernel<<<(G + 127) / 128, 256>>>(
        (const float*)pS, (const __nv_bfloat16*)pB2h, (const __nv_bfloat16*)pB2l,
        bk, nullptr, out, G);
}